// round 1
// baseline (speedup 1.0000x reference)
#include <cuda_runtime.h>

#define N1 262144
#define N2 65536
#define KNN 16
#define MPAIR (N2*KNN)
#define EPSV 1e-5f

// ---- static scratch (no runtime allocation allowed) ----
__device__ float    g_upfeat[N2*64];   // relu(bn(x2@w2^T))            16 MB
__device__ float    g_pre[N2*64];      // x2-part of shrinker linear   16 MB
__device__ float    g_logit[MPAIR];    //                               4 MB
__device__ float    g_e[MPAIR];        //                               4 MB
__device__ unsigned g_gmax[N1];        // order-encoded segment max     1 MB
__device__ float    g_denom[N1];       // softmax denominator           1 MB

// monotone float -> uint encoding (so atomicMax works on floats)
__device__ __forceinline__ unsigned enc_f(float f) {
    unsigned u = __float_as_uint(f);
    return (u & 0x80000000u) ? ~u : (u | 0x80000000u);
}
__device__ __forceinline__ float dec_f(unsigned u) {
    return __uint_as_float((u & 0x80000000u) ? (u ^ 0x80000000u) : ~u);
}

__global__ void init_kernel() {
    int i = blockIdx.x * blockDim.x + threadIdx.x;
    if (i < N1) { g_gmax[i] = 0u; g_denom[i] = 0.0f; }
}

// Generic fused Linear(64->64)+BN(+ReLU). Weight row stride / column offset
// parameters let it also slice ws1[:, 3:67]. DST: 0 -> outp, 1 -> g_upfeat, 2 -> g_pre.
template<bool RELU, int DST>
__global__ void matvec64_kernel(const float* __restrict__ x, int n,
                                const float* __restrict__ w, int wstride, int wcol0,
                                const float* __restrict__ b,
                                const float* __restrict__ g,
                                const float* __restrict__ be,
                                const float* __restrict__ m,
                                const float* __restrict__ v,
                                float* __restrict__ outp)
{
    const int c = threadIdx.x;   // 0..63 output channel
    const int p = threadIdx.y;   // 0..3  point slot
    float s  = g[c] * rsqrtf(v[c] + EPSV);
    float fb = (b[c] - m[c]) * s + be[c];          // BN folded bias
    float wreg[64];
    #pragma unroll
    for (int d = 0; d < 64; d++) wreg[d] = w[c * wstride + wcol0 + d] * s;

    float* o = (DST == 0) ? outp : ((DST == 1) ? g_upfeat : g_pre);
    __shared__ float xs[4][64];

    for (int base = blockIdx.x * 4; base < n; base += gridDim.x * 4) {
        int pt = base + p;                          // n % 4 == 0 -> always valid
        xs[p][c] = x[pt * 64 + c];                  // coalesced load
        __syncthreads();
        float acc = fb;
        const float4* xv = (const float4*)xs[p];    // broadcast LDS.128 within warp
        #pragma unroll
        for (int d4 = 0; d4 < 16; d4++) {
            float4 xq = xv[d4];
            acc = fmaf(xq.x, wreg[4*d4+0], acc);
            acc = fmaf(xq.y, wreg[4*d4+1], acc);
            acc = fmaf(xq.z, wreg[4*d4+2], acc);
            acc = fmaf(xq.w, wreg[4*d4+3], acc);
        }
        if (RELU) acc = fmaxf(acc, 0.0f);
        o[pt * 64 + c] = acc;
        __syncthreads();
    }
}

// Per-pair logit: h_c = relu(pre[j][c] + p_r . w3[c]); logit = sum h_c*ws2[c] + bs2
// Then atomicMax into the segment max keyed by the dense point index.
__global__ void logit_kernel(const float* __restrict__ p1,
                             const float* __restrict__ p2,
                             const int*   __restrict__ knn,
                             const float* __restrict__ ws1,
                             const float* __restrict__ gsv,
                             const float* __restrict__ vsv,
                             const float* __restrict__ ws2,
                             const float* __restrict__ bs2)
{
    __shared__ float sw3[64][3];
    __shared__ float sw2[64];
    int tid = threadIdx.x;
    if (tid < 64) {
        float s = gsv[tid] * rsqrtf(vsv[tid] + EPSV);
        sw3[tid][0] = ws1[tid * 67 + 0] * s;
        sw3[tid][1] = ws1[tid * 67 + 1] * s;
        sw3[tid][2] = ws1[tid * 67 + 2] * s;
        sw2[tid]    = ws2[tid];
    }
    __syncthreads();

    int mi = blockIdx.x * blockDim.x + tid;         // one pair per thread
    int j  = mi >> 4;                               // coarse point
    int i  = knn[mi];                               // dense point (scatter key)
    float prx = p1[i*3+0] - p2[j*3+0];
    float pry = p1[i*3+1] - p2[j*3+1];
    float prz = p1[i*3+2] - p2[j*3+2];

    float acc = 0.0f;
    const float4* pre4 = (const float4*)(g_pre + (size_t)j * 64);
    #pragma unroll
    for (int c4 = 0; c4 < 16; c4++) {
        float4 pv = pre4[c4];                       // 16 lanes share j -> L1 broadcast
        int c = c4 * 4;
        float h;
        h = fmaf(prx, sw3[c+0][0], fmaf(pry, sw3[c+0][1], fmaf(prz, sw3[c+0][2], pv.x)));
        h = fmaxf(h, 0.0f); acc = fmaf(h, sw2[c+0], acc);
        h = fmaf(prx, sw3[c+1][0], fmaf(pry, sw3[c+1][1], fmaf(prz, sw3[c+1][2], pv.y)));
        h = fmaxf(h, 0.0f); acc = fmaf(h, sw2[c+1], acc);
        h = fmaf(prx, sw3[c+2][0], fmaf(pry, sw3[c+2][1], fmaf(prz, sw3[c+2][2], pv.z)));
        h = fmaxf(h, 0.0f); acc = fmaf(h, sw2[c+2], acc);
        h = fmaf(prx, sw3[c+3][0], fmaf(pry, sw3[c+3][1], fmaf(prz, sw3[c+3][2], pv.w)));
        h = fmaxf(h, 0.0f); acc = fmaf(h, sw2[c+3], acc);
    }
    float lg = acc + bs2[0];
    g_logit[mi] = lg;
    atomicMax(&g_gmax[i], enc_f(lg));
}

// exp(logit - segmax) + denom accumulation
__global__ void exp_kernel(const int* __restrict__ knn) {
    int mi = blockIdx.x * blockDim.x + threadIdx.x;
    int i  = knn[mi];
    float ev = __expf(g_logit[mi] - dec_f(g_gmax[i]));
    g_e[mi] = ev;
    atomicAdd(&g_denom[i], ev);
}

// Weighted scatter: out[idx] += up_feat[j] * prob. One warp per pair;
// lane handles channels {lane, lane+32} -> coalesced 128B atomic lines.
__global__ void scatter_kernel(const int* __restrict__ knn, float* __restrict__ out) {
    int gw   = (blockIdx.x * blockDim.x + threadIdx.x) >> 5;
    int lane = threadIdx.x & 31;
    #pragma unroll
    for (int r = 0; r < 4; r++) {
        int mi = gw * 4 + r;
        int j  = mi >> 4;
        int i  = knn[mi];
        float prob = g_e[mi] / g_denom[i];
        float u0 = g_upfeat[(size_t)j * 64 + lane];
        float u1 = g_upfeat[(size_t)j * 64 + 32 + lane];
        atomicAdd(&out[(size_t)i * 64 + lane],      u0 * prob);
        atomicAdd(&out[(size_t)i * 64 + 32 + lane], u1 * prob);
    }
}

extern "C" void kernel_launch(void* const* d_in, const int* in_sizes, int n_in,
                              void* d_out, int out_size)
{
    const float* p1  = (const float*)d_in[0];
    const float* p2  = (const float*)d_in[1];
    const float* x1  = (const float*)d_in[2];
    const float* x2  = (const float*)d_in[3];
    const int*   knn = (const int*)  d_in[4];
    const float* w1  = (const float*)d_in[5];
    const float* b1  = (const float*)d_in[6];
    const float* g1  = (const float*)d_in[7];
    const float* be1 = (const float*)d_in[8];
    const float* m1  = (const float*)d_in[9];
    const float* v1  = (const float*)d_in[10];
    const float* w2  = (const float*)d_in[11];
    const float* b2  = (const float*)d_in[12];
    const float* g2  = (const float*)d_in[13];
    const float* be2 = (const float*)d_in[14];
    const float* m2  = (const float*)d_in[15];
    const float* v2  = (const float*)d_in[16];
    const float* ws1 = (const float*)d_in[17];
    const float* bs1 = (const float*)d_in[18];
    const float* gs  = (const float*)d_in[19];
    const float* bes = (const float*)d_in[20];
    const float* ms  = (const float*)d_in[21];
    const float* vs  = (const float*)d_in[22];
    const float* ws2 = (const float*)d_in[23];
    const float* bs2 = (const float*)d_in[24];
    float* out = (float*)d_out;

    dim3 mv(64, 4);

    init_kernel<<<N1/256, 256>>>();

    // skip branch: y1 -> d_out (initializes every output element)
    matvec64_kernel<true, 0><<<1024, mv>>>(x1, N1, w1, 64, 0, b1, g1, be1, m1, v1, out);
    // up_feat = relu(bn(x2 @ w2^T))
    matvec64_kernel<true, 1><<<512, mv>>>(x2, N2, w2, 64, 0, b2, g2, be2, m2, v2, nullptr);
    // pre = x2-part of channel_shrinker first linear (BN folded, no relu yet)
    matvec64_kernel<false, 2><<<512, mv>>>(x2, N2, ws1, 67, 3, bs1, gs, bes, ms, vs, nullptr);

    logit_kernel<<<MPAIR/256, 256>>>(p1, p2, knn, ws1, gs, vs, ws2, bs2);
    exp_kernel<<<MPAIR/256, 256>>>(knn);
    scatter_kernel<<<MPAIR/4/8, 256>>>(knn, out);
}

// round 2
// speedup vs baseline: 2.1581x; 2.1581x over previous
#include <cuda_runtime.h>

#define N1 262144
#define N2 65536
#define KNN 16
#define MPAIR (N2*KNN)
#define EPSV 1e-5f

// ---- static scratch (no runtime allocation allowed) ----
__device__ float g_upfeat[N2*64];   // relu(bn(x2@w2^T))            16 MB
__device__ float g_pre[N2*64];      // x2-part of shrinker linear   16 MB
__device__ float g_e[MPAIR];        // exp(logit)                    4 MB
__device__ float g_denom[N1];       // softmax denominator           1 MB

__global__ void init_kernel() {
    int i = blockIdx.x * blockDim.x + threadIdx.x;
    if (i < N1) g_denom[i] = 0.0f;
}

// Fused Linear(64->64)+BN(+ReLU) as a register-blocked GEMM.
// Per block: 128 points x 64 channels, K=64 (full). 128 threads, each owns
// an 8x8 register tile. x tile in smem (conflict-free broadcast reads),
// BN-folded W in smem with an XOR swizzle so w-loads are bank-conflict-free.
// DST: 0 -> outp, 1 -> g_upfeat, 2 -> g_pre.
template<bool RELU, int DST>
__global__ void __launch_bounds__(128, 4)
gemm64_kernel(const float* __restrict__ x,
              const float* __restrict__ w, int wstride, int wcol0,
              const float* __restrict__ b,
              const float* __restrict__ g,
              const float* __restrict__ be,
              const float* __restrict__ m,
              const float* __restrict__ v,
              float* __restrict__ outp)
{
    __shared__ __align__(16) float xs[128][64];   // 32 KB
    __shared__ __align__(16) float ws[64 * 64];   // 16 KB, swizzled: total 48 KB

    const int tid = threadIdx.x;
    const int tc  = tid & 7;       // channel group 0..7
    const int tp  = tid >> 3;      // point slot   0..15
    const int base = blockIdx.x * 128;

    // ---- load x tile: fully coalesced linear float4 ----
    const float4* gx = (const float4*)(x + (size_t)base * 64);
    #pragma unroll
    for (int i = 0; i < 16; i++) {
        int idx = i * 128 + tid;              // 0..2047
        int p = idx >> 4, k4 = idx & 15;
        *(float4*)&xs[p][4 * k4] = gx[idx];   // conflict-free STS.128
    }

    // ---- fold BN into W and store swizzled ----
    // phys(c,k) = c*64 + 4*(((k>>2)+(c>>2)) & 15) + (k&3)
    #pragma unroll
    for (int it = 0; it < 32; it++) {
        int idx = it * 128 + tid;             // 0..4095
        int c = idx >> 6, k = idx & 63;
        float s = g[c] * rsqrtf(v[c] + EPSV);
        float val = w[c * wstride + wcol0 + k] * s;
        int col = 4 * (((k >> 2) + (c >> 2)) & 15) + (k & 3);
        ws[c * 64 + col] = val;
    }

    // ---- per-thread channels: c = h*32 + 4*tc + j  (h=0,1; j=0..3) ----
    float acc[8][8];   // [pp][h*4+j], init with folded bias
    #pragma unroll
    for (int h = 0; h < 2; h++)
        #pragma unroll
        for (int j = 0; j < 4; j++) {
            int c = h * 32 + 4 * tc + j;
            float s  = g[c] * rsqrtf(v[c] + EPSV);
            float fb = (b[c] - m[c]) * s + be[c];
            #pragma unroll
            for (int pp = 0; pp < 8; pp++) acc[pp][h * 4 + j] = fb;
        }

    __syncthreads();

    // ---- main loop over K in float4 steps ----
    #pragma unroll
    for (int k4 = 0; k4 < 16; k4++) {
        float4 wq[8];
        int col0 = 4 * ((k4 + tc) & 15);      // swizzle for h=0 (c>>2 == tc)
        int col1 = 4 * ((k4 + tc + 8) & 15);  // swizzle for h=1 (c>>2 == tc+8)
        #pragma unroll
        for (int j = 0; j < 4; j++) {
            wq[j]     = *(float4*)&ws[(4 * tc + j) * 64 + col0];
            wq[4 + j] = *(float4*)&ws[(32 + 4 * tc + j) * 64 + col1];
        }
        #pragma unroll
        for (int pp = 0; pp < 8; pp++) {
            float4 xq = *(float4*)&xs[16 * pp + tp][4 * k4];  // broadcast in phase
            #pragma unroll
            for (int ch = 0; ch < 8; ch++) {
                acc[pp][ch] = fmaf(xq.x, wq[ch].x, acc[pp][ch]);
                acc[pp][ch] = fmaf(xq.y, wq[ch].y, acc[pp][ch]);
                acc[pp][ch] = fmaf(xq.z, wq[ch].z, acc[pp][ch]);
                acc[pp][ch] = fmaf(xq.w, wq[ch].w, acc[pp][ch]);
            }
        }
    }

    // ---- write out: 2 coalesced STG.128 per point-slot ----
    float* o = (DST == 0) ? outp : ((DST == 1) ? g_upfeat : g_pre);
    #pragma unroll
    for (int pp = 0; pp < 8; pp++) {
        int p = base + 16 * pp + tp;
        #pragma unroll
        for (int h = 0; h < 2; h++) {
            float4 ov;
            ov.x = acc[pp][h * 4 + 0];
            ov.y = acc[pp][h * 4 + 1];
            ov.z = acc[pp][h * 4 + 2];
            ov.w = acc[pp][h * 4 + 3];
            if (RELU) {
                ov.x = fmaxf(ov.x, 0.f); ov.y = fmaxf(ov.y, 0.f);
                ov.z = fmaxf(ov.z, 0.f); ov.w = fmaxf(ov.w, 0.f);
            }
            *(float4*)&o[(size_t)p * 64 + h * 32 + 4 * tc] = ov;
        }
    }
}

// Per-pair logit + exp + denom accumulation (segment max dropped: logits are
// O(1), exp cannot overflow, prob = e/sum(e) is mathematically identical).
__global__ void logit_kernel(const float* __restrict__ p1,
                             const float* __restrict__ p2,
                             const int*   __restrict__ knn,
                             const float* __restrict__ ws1,
                             const float* __restrict__ gsv,
                             const float* __restrict__ vsv,
                             const float* __restrict__ ws2,
                             const float* __restrict__ bs2)
{
    __shared__ float sw3[64][3];
    __shared__ float sw2[64];
    int tid = threadIdx.x;
    if (tid < 64) {
        float s = gsv[tid] * rsqrtf(vsv[tid] + EPSV);
        sw3[tid][0] = ws1[tid * 67 + 0] * s;
        sw3[tid][1] = ws1[tid * 67 + 1] * s;
        sw3[tid][2] = ws1[tid * 67 + 2] * s;
        sw2[tid]    = ws2[tid];
    }
    __syncthreads();

    int mi = blockIdx.x * blockDim.x + tid;
    int j  = mi >> 4;                 // coarse point (16 lanes share j)
    int i  = knn[mi];                 // dense point (scatter key)
    float prx = p1[i*3+0] - p2[j*3+0];
    float pry = p1[i*3+1] - p2[j*3+1];
    float prz = p1[i*3+2] - p2[j*3+2];

    float acc = 0.0f;
    const float4* pre4 = (const float4*)(g_pre + (size_t)j * 64);
    #pragma unroll
    for (int c4 = 0; c4 < 16; c4++) {
        float4 pv = pre4[c4];
        int c = c4 * 4;
        float h;
        h = fmaf(prx, sw3[c+0][0], fmaf(pry, sw3[c+0][1], fmaf(prz, sw3[c+0][2], pv.x)));
        h = fmaxf(h, 0.0f); acc = fmaf(h, sw2[c+0], acc);
        h = fmaf(prx, sw3[c+1][0], fmaf(pry, sw3[c+1][1], fmaf(prz, sw3[c+1][2], pv.y)));
        h = fmaxf(h, 0.0f); acc = fmaf(h, sw2[c+1], acc);
        h = fmaf(prx, sw3[c+2][0], fmaf(pry, sw3[c+2][1], fmaf(prz, sw3[c+2][2], pv.z)));
        h = fmaxf(h, 0.0f); acc = fmaf(h, sw2[c+2], acc);
        h = fmaf(prx, sw3[c+3][0], fmaf(pry, sw3[c+3][1], fmaf(prz, sw3[c+3][2], pv.w)));
        h = fmaxf(h, 0.0f); acc = fmaf(h, sw2[c+3], acc);
    }
    float ev = __expf(acc + bs2[0]);
    g_e[mi] = ev;
    atomicAdd(&g_denom[i], ev);
}

// Weighted scatter: out[idx] += up_feat[j] * prob. One warp per pair;
// lanes cover channels {lane, lane+32} -> two 128B atomic lines per pair.
__global__ void scatter_kernel(const int* __restrict__ knn, float* __restrict__ out) {
    int gw   = (blockIdx.x * blockDim.x + threadIdx.x) >> 5;
    int lane = threadIdx.x & 31;
    #pragma unroll
    for (int r = 0; r < 4; r++) {
        int mi = gw * 4 + r;
        int j  = mi >> 4;
        int i  = knn[mi];
        float prob = g_e[mi] / g_denom[i];
        float u0 = g_upfeat[(size_t)j * 64 + lane];
        float u1 = g_upfeat[(size_t)j * 64 + 32 + lane];
        atomicAdd(&out[(size_t)i * 64 + lane],      u0 * prob);
        atomicAdd(&out[(size_t)i * 64 + 32 + lane], u1 * prob);
    }
}

extern "C" void kernel_launch(void* const* d_in, const int* in_sizes, int n_in,
                              void* d_out, int out_size)
{
    const float* p1  = (const float*)d_in[0];
    const float* p2  = (const float*)d_in[1];
    const float* x1  = (const float*)d_in[2];
    const float* x2  = (const float*)d_in[3];
    const int*   knn = (const int*)  d_in[4];
    const float* w1  = (const float*)d_in[5];
    const float* b1  = (const float*)d_in[6];
    const float* g1  = (const float*)d_in[7];
    const float* be1 = (const float*)d_in[8];
    const float* m1  = (const float*)d_in[9];
    const float* v1  = (const float*)d_in[10];
    const float* w2  = (const float*)d_in[11];
    const float* b2  = (const float*)d_in[12];
    const float* g2  = (const float*)d_in[13];
    const float* be2 = (const float*)d_in[14];
    const float* m2  = (const float*)d_in[15];
    const float* v2  = (const float*)d_in[16];
    const float* ws1 = (const float*)d_in[17];
    const float* bs1 = (const float*)d_in[18];
    const float* gs  = (const float*)d_in[19];
    const float* bes = (const float*)d_in[20];
    const float* ms  = (const float*)d_in[21];
    const float* vs  = (const float*)d_in[22];
    const float* ws2 = (const float*)d_in[23];
    const float* bs2 = (const float*)d_in[24];
    float* out = (float*)d_out;

    init_kernel<<<N1/256, 256>>>();

    // skip branch: y1 -> d_out (initializes every output element)
    gemm64_kernel<true, 0><<<N1/128, 128>>>(x1, w1, 64, 0, b1, g1, be1, m1, v1, out);
    // up_feat = relu(bn(x2 @ w2^T))
    gemm64_kernel<true, 1><<<N2/128, 128>>>(x2, w2, 64, 0, b2, g2, be2, m2, v2, nullptr);
    // pre = x2-part of channel_shrinker first linear (BN folded, no relu yet)
    gemm64_kernel<false, 2><<<N2/128, 128>>>(x2, ws1, 67, 3, bs1, gs, bes, ms, vs, nullptr);

    // logit + exp + denom in one MPAIR pass
    logit_kernel<<<MPAIR/256, 256>>>(p1, p2, knn, ws1, gs, vs, ws2, bs2);
    // weighted scatter on top of y1
    scatter_kernel<<<MPAIR/4/8, 256>>>(knn, out);
}